// round 4
// baseline (speedup 1.0000x reference)
#include <cuda_runtime.h>
#include <math.h>

#define NQ 50
#define NS 64
#define NP 3
#define TW 128          // words per inner tile
#define NT 256          // threads per block
#define CH 10           // qubits per staged chunk
#define NCHUNK 5
#define SROW 31         // slab row stride (odd -> conflict-free)
#define GRID (148*3)

typedef unsigned long long u64;

// Precomputed head tables (device globals: no allocation allowed)
// g_h01[q*32 + pair] = {H0[2p], H0[2p+1], H1[2p], H1[2p+1]}
__device__ float4 g_h01[NQ * NS / 2];
__device__ float  g_hr[NS];          // hr'_s = hr_s * K_s

// ---------------- packed f32x2 helpers ----------------
__device__ __forceinline__ u64 pack2(float x, float y) {
    u64 r;
    asm("mov.b64 %0, {%1, %2};" : "=l"(r) : "f"(x), "f"(y));
    return r;
}
__device__ __forceinline__ void unpack2(u64 v, float &x, float &y) {
    asm("mov.b64 {%0, %1}, %2;" : "=f"(x), "=f"(y) : "l"(v));
}
__device__ __forceinline__ u64 fma2(u64 a, u64 b, u64 c) {
    u64 d;
    asm("fma.rn.f32x2 %0, %1, %2, %3;" : "=l"(d) : "l"(a), "l"(b), "l"(c));
    return d;
}
__device__ __forceinline__ u64 mul2(u64 a, u64 b) {
    u64 d;
    asm("mul.rn.f32x2 %0, %1, %2;" : "=l"(d) : "l"(a), "l"(b));
    return d;
}

// softplus(20x), overflow-safe
__device__ __forceinline__ float sp20(float x) {
    float y = 20.0f * x;
    return fmaxf(y, 0.0f) + log1pf(expf(-fabsf(y)));
}

// ---------------- prep: heads + ratios ----------------
__global__ void __launch_bounds__(512)
prep_kernel(const float* __restrict__ heads_param,
            const float* __restrict__ hr_param,
            float* __restrict__ out) {
    __shared__ float sh0[NQ][NS];
    __shared__ float sh1[NQ][NS];
    __shared__ float shK[8][NS];
    __shared__ float ssum[NS];

    int s  = threadIdx.x;   // 64
    int qt = threadIdx.y;   // 8
    int tid = s + NS * qt;

    if (tid == 0) out[0] = 0.0f;   // d_out is poisoned; zero every launch

    float K = 1.0f;
    for (int q = qt; q < NQ; q += 8) {
        const float* p = heads_param + (s * NQ + q) * NP;
        float a = sp20(p[0]);
        float b = sp20(p[1]);
        float c = sp20(p[2]);
        float sum = a + b + c;
        float E = fmaxf(sum, 1e-12f);
        float hsum = sum / E;                   // == 1.0 unless sum < eps
        float inv = 1.0f / fmaxf(sum, 1e-30f);
        sh0[q][s] = a * inv;
        sh1[q][s] = b * inv;
        K *= hsum;
    }
    shK[qt][s] = K;
    if (qt == 0) ssum[s] = sp20(hr_param[s]);
    __syncthreads();

    if (qt == 0) {
        float Ks = 1.0f;
        #pragma unroll
        for (int i = 0; i < 8; i++) Ks *= shK[i][s];
        float tot = 0.0f;
        #pragma unroll
        for (int i = 0; i < NS; i++) tot += ssum[i];
        tot = fmaxf(tot, 1e-12f);
        float r = ssum[s] / tot;
        r = (r + 0.001f / 64.0f) / 1.001f;
        g_hr[s] = r * Ks;
    }

    for (int i = tid; i < NQ * NS / 2; i += 512) {
        int q = i >> 5;
        int pr = i & 31;
        g_h01[i] = make_float4(sh0[q][2 * pr], sh0[q][2 * pr + 1],
                               sh1[q][2 * pr], sh1[q][2 * pr + 1]);
    }
}

// ---------------- main (persistent, balanced ranges) ----------------
__global__ void __launch_bounds__(NT, 3)
main_kernel(const float* __restrict__ pauli,
            const float* __restrict__ coeff,
            float* __restrict__ out, int N) {
    __shared__ __align__(16) float4 sh_h[NQ * 32];          // 25600 B
    __shared__ __align__(16) float  sh_hr[NS];              // 256 B
    __shared__ __align__(16) float  slab[TW * SROW];        // 15872 B
    __shared__ float ph[TW][4];                             // 2048 B
    __shared__ float red[NT / 32];

    int tid  = threadIdx.x;
    int lane = tid & 31;
    int wid  = tid >> 5;
    int w    = tid & 63;       // first word slot; second is w+64
    int hg   = tid >> 6;       // head group 0..3 (8 pairs each), warp-uniform

    // balanced contiguous word range for this CTA
    long long g = blockIdx.x;
    int n0r = (int)((g * (long long)N) / GRID);
    int n1r = (int)(((g + 1) * (long long)N) / GRID);

    // Stage heads + ratios once per CTA
    for (int i = tid; i < NQ * 32; i += NT) sh_h[i] = g_h01[i];
    if (tid < NS) sh_hr[tid] = g_hr[tid];

    float term = 0.0f;

    for (int n0 = n0r; n0 < n1r; n0 += TW) {
        int count = min(TW, n1r - n0);

        u64 prod[16];
        #pragma unroll
        for (int i = 0; i < 16; i++) prod[i] = 0x3F8000003F800000ULL;  // {1,1}

        for (int ch = 0; ch < NCHUNK; ch++) {
            __syncthreads();   // protect slab reuse (also covers sh_h on first pass)
            int q0 = ch * CH;
            {   // coalesced stage: count*30 floats
                const float* src = pauli + (size_t)n0 * (NQ * NP) + q0 * NP;
                int total = count * (CH * NP);
                for (int i = tid; i < total; i += NT) {
                    int r = i / (CH * NP);
                    int c = i - r * (CH * NP);
                    slab[r * SROW + c] = src[(size_t)r * (NQ * NP) + c];
                }
            }
            __syncthreads();

            const float* prowA = slab + w * SROW;
            const float* prowB = prowA + 64 * SROW;
            const double2* hq = (const double2*)sh_h + q0 * 32 + hg * 8;

            #pragma unroll 2
            for (int qq = 0; qq < CH; qq++) {
                float a0 = prowA[0], a1 = prowA[1], a2 = prowA[2];
                float b0 = prowB[0], b1 = prowB[1], b2 = prowB[2];
                prowA += 3; prowB += 3;
                u64 da0 = pack2(a0 - a2, a0 - a2);
                u64 da1 = pack2(a1 - a2, a1 - a2);
                u64 pa  = pack2(a2, a2);
                u64 db0 = pack2(b0 - b2, b0 - b2);
                u64 db1 = pack2(b1 - b2, b1 - b2);
                u64 pb  = pack2(b2, b2);
                #pragma unroll
                for (int i = 0; i < 8; i++) {
                    double2 h = hq[i];                   // broadcast LDS.128
                    u64 h0 = __double_as_longlong(h.x);
                    u64 h1 = __double_as_longlong(h.y);
                    u64 t = fma2(h1, da1, pa);
                    t = fma2(h0, da0, t);
                    prod[i] = mul2(prod[i], t);
                    u64 u = fma2(h1, db1, pb);
                    u = fma2(h0, db0, u);
                    prod[8 + i] = mul2(prod[8 + i], u);
                }
                hq += 32;
            }
        }

        // partial cov over this thread's 16 heads, both words
        u64 accA = 0ULL, accB = 0ULL;
        const u64* hr2 = (const u64*)sh_hr + hg * 8;
        #pragma unroll
        for (int i = 0; i < 8; i++) {
            accA = fma2(hr2[i], prod[i], accA);
            accB = fma2(hr2[i], prod[8 + i], accB);
        }
        float xl, xh;
        unpack2(accA, xl, xh);
        ph[w][hg] = xl + xh;
        __syncthreads();          // ph[w] slots done for hg of word w? need both writes
        unpack2(accB, xl, xh);
        ph[w + 64][hg] = xl + xh;
        __syncthreads();

        if (tid < count) {
            float cov = ph[tid][0] + ph[tid][1] + ph[tid][2] + ph[tid][3];
            float c = coeff[n0 + tid];
            term += (c * c) / cov;
        }
        __syncthreads();          // all reads done before next tile reuses ph/slab
    }

    // block reduction
    #pragma unroll
    for (int off = 16; off > 0; off >>= 1)
        term += __shfl_down_sync(0xFFFFFFFFu, term, off);
    if (lane == 0) red[wid] = term;
    __syncthreads();
    if (tid == 0) {
        float t = 0.0f;
        #pragma unroll
        for (int i = 0; i < NT / 32; i++) t += red[i];
        atomicAdd(out, t);
    }
}

extern "C" void kernel_launch(void* const* d_in, const int* in_sizes, int n_in,
                              void* d_out, int out_size) {
    const float* pauli = (const float*)d_in[0];   // [N, 50, 3] f32
    const float* coeff = (const float*)d_in[1];   // [N] f32
    const float* hp    = (const float*)d_in[2];   // [64, 50, 3] f32
    const float* hrp   = (const float*)d_in[3];   // [64] f32
    float* out = (float*)d_out;
    int N = in_sizes[1];

    prep_kernel<<<1, dim3(NS, 8)>>>(hp, hrp, out);
    main_kernel<<<GRID, NT>>>(pauli, coeff, out, N);
}